// round 7
// baseline (speedup 1.0000x reference)
#include <cuda_runtime.h>
#include <cuda_bf16.h>
#include <math.h>
#include <stdint.h>

#define HEADS   16
#define D_MODEL 1024
#define DK      64
#define BATCH   2
#define SEQ     2048
#define MROWS   (BATCH * SEQ)   // 4096
#define MD      (MROWS * D_MODEL)
#define DD      (D_MODEL * D_MODEL)

// ---------------- scratch (device globals; no allocation allowed) ----------
__device__ __align__(16) __nv_bfloat16 g_x3h[3 * MD];   // split q/k/v inputs hi
__device__ __align__(16) __nv_bfloat16 g_x3l[3 * MD];   // lo
__device__ __align__(16) __nv_bfloat16 g_w4h[4 * DD];   // W^T hi [N][K] x4 (q,k,v,o)
__device__ __align__(16) __nv_bfloat16 g_w4l[4 * DD];
__device__ __align__(16) __nv_bfloat16 g_ah[MD];        // attn output hi [B,S,D]
__device__ __align__(16) __nv_bfloat16 g_al[MD];
__device__ __align__(16) __nv_bfloat16 g_qh[MD];        // [bh][s][d] (pre-scaled 1/8)
__device__ __align__(16) __nv_bfloat16 g_ql[MD];
__device__ __align__(16) __nv_bfloat16 g_kh[MD];        // [bh][s][d]
__device__ __align__(16) __nv_bfloat16 g_kl[MD];
__device__ __align__(16) __nv_bfloat16 g_vth[MD];       // [bh][d][s]
__device__ __align__(16) __nv_bfloat16 g_vtl[MD];

// ---------------------------------------------------------------------------
__device__ __forceinline__ uint32_t smem_u32(const void* p) {
    uint32_t a;
    asm("{ .reg .u64 t; cvta.to.shared.u64 t, %1; cvt.u32.u64 %0, t; }"
        : "=r"(a) : "l"(p));
    return a;
}
__device__ __forceinline__ void cpasync16(uint32_t dst, const void* src) {
    asm volatile("cp.async.cg.shared.global [%0], [%1], 16;"
                 :: "r"(dst), "l"(src) : "memory");
}
__device__ __forceinline__ void ldsm4(uint32_t a, uint32_t& r0, uint32_t& r1,
                                      uint32_t& r2, uint32_t& r3) {
    asm volatile("ldmatrix.sync.aligned.m8n8.x4.shared.b16 {%0,%1,%2,%3}, [%4];"
                 : "=r"(r0), "=r"(r1), "=r"(r2), "=r"(r3) : "r"(a));
}
__device__ __forceinline__ void mma_bf16(float* c, const uint32_t* a, const uint32_t* b) {
    asm volatile(
        "mma.sync.aligned.m16n8k16.row.col.f32.bf16.bf16.f32 "
        "{%0,%1,%2,%3}, {%4,%5,%6,%7}, {%8,%9}, {%0,%1,%2,%3};"
        : "+f"(c[0]), "+f"(c[1]), "+f"(c[2]), "+f"(c[3])
        : "r"(a[0]), "r"(a[1]), "r"(a[2]), "r"(a[3]), "r"(b[0]), "r"(b[1]));
}
__device__ __forceinline__ uint32_t pack_bf16(float x, float y) {
    uint32_t r;
    asm("cvt.rn.bf16x2.f32 %0, %1, %2;" : "=r"(r) : "f"(y), "f"(x));
    return r;
}
__device__ __forceinline__ void split2(float x, float y, uint32_t& hi, uint32_t& lo) {
    hi = pack_bf16(x, y);
    const float hx = __uint_as_float(hi << 16);
    const float hy = __uint_as_float(hi & 0xffff0000u);
    lo = pack_bf16(x - hx, y - hy);
}

// ---------------------------------------------------------------------------
// split3: q/k/v inputs fp32 -> bf16 hi/lo (blockIdx.y selects source)
// ---------------------------------------------------------------------------
__global__ __launch_bounds__(256) void split3_kernel(const float* __restrict__ q,
                                                     const float* __restrict__ k,
                                                     const float* __restrict__ v)
{
    const int z = blockIdx.y;
    const float* src = (z == 0) ? q : (z == 1) ? k : v;
    uint32_t* dh = (uint32_t*)(g_x3h + (size_t)z * MD);
    uint32_t* dl = (uint32_t*)(g_x3l + (size_t)z * MD);
    const int i = blockIdx.x * 256 + threadIdx.x;          // float4 index
    const float4 x = ((const float4*)src)[i];
    uint32_t h0, l0, h1, l1;
    split2(x.x, x.y, h0, l0);
    split2(x.z, x.w, h1, l1);
    dh[i * 2 + 0] = h0;  dh[i * 2 + 1] = h1;
    dl[i * 2 + 0] = l0;  dl[i * 2 + 1] = l1;
}

// splitT4: all four W [K][N] fp32 -> W^T hi/lo [N][K] (blockIdx.z selects)
__global__ __launch_bounds__(256) void splitT4_kernel(const float* __restrict__ Wq,
                                                      const float* __restrict__ Wk,
                                                      const float* __restrict__ Wv,
                                                      const float* __restrict__ Wo)
{
    __shared__ float tile[32][33];
    const int z = blockIdx.z;
    const float* W = (z == 0) ? Wq : (z == 1) ? Wk : (z == 2) ? Wv : Wo;
    __nv_bfloat16* wh = g_w4h + (size_t)z * DD;
    __nv_bfloat16* wl = g_w4l + (size_t)z * DD;
    const int bx = blockIdx.x * 32, by = blockIdx.y * 32;
    const int tx = threadIdx.x, ty = threadIdx.y;          // 32 x 8
    #pragma unroll
    for (int k = 0; k < 32; k += 8)
        tile[ty + k][tx] = W[(size_t)(by + ty + k) * D_MODEL + bx + tx];
    __syncthreads();
    #pragma unroll
    for (int k = 0; k < 32; k += 8) {
        const float v = tile[tx][ty + k];
        const __nv_bfloat16 h = __float2bfloat16(v);
        const size_t o = (size_t)(bx + ty + k) * D_MODEL + by + tx;
        wh[o] = h;
        wl[o] = __float2bfloat16(v - __bfloat162float(h));
    }
}

// ---------------------------------------------------------------------------
// mma.sync bf16x3 GEMM, 3-stage cp.async pipeline.
// FUSED=1: QKV projections (blockIdx.z = 0/1/2 -> q/k/v dest layouts)
// FUSED=0: output projection (A = g_ah/g_al, W index 3, C fp32 row-major)
// ---------------------------------------------------------------------------
#define PITCHB   80                       // bytes per smem row (40 halves)
#define TILE_B   (128 * PITCHB)           // 10240 B per tile
#define BUF_B    (4 * TILE_B)             // 40960 B per stage
#define NSTAGE   3
#define GM_SMEM  (NSTAGE * BUF_B)         // 122880 B

template<int FUSED>
__global__ void __launch_bounds__(256) gemm_mma(const float* __restrict__ b0,
                                                const float* __restrict__ b1,
                                                const float* __restrict__ b2,
                                                float* __restrict__ C)
{
    extern __shared__ char smc[];
    const uint32_t sb = smem_u32(smc);
    const int z = FUSED ? blockIdx.z : 3;
    const __nv_bfloat16* Ah = FUSED ? g_x3h + (size_t)z * MD : g_ah;
    const __nv_bfloat16* Al = FUSED ? g_x3l + (size_t)z * MD : g_al;
    const __nv_bfloat16* Wh = g_w4h + (size_t)z * DD;
    const __nv_bfloat16* Wl = g_w4l + (size_t)z * DD;
    const float* bias = FUSED ? ((z == 0) ? b0 : (z == 1) ? b1 : b2) : b0;

    const int tid  = threadIdx.x;
    const int lane = tid & 31, wid = tid >> 5;
    const int wm = wid & 3, wn = wid >> 2;       // warp tile (wm*32, wn*64)
    const int m0 = blockIdx.y * 128;
    const int n0 = blockIdx.x * 128;
    const int gr = lane >> 2;                    // 0..7
    const int gc = (lane & 3) << 1;              // 0,2,4,6
    const int aRow  = lane & 15;
    const int aKoff = (lane >> 4) << 4;
    const int bRow  = ((lane >> 4) << 3) | (lane & 7);
    const int bKoff = ((lane >> 3) & 1) << 4;

    float acc[2][8][4];
    #pragma unroll
    for (int mt = 0; mt < 2; mt++)
        #pragma unroll
        for (int nf = 0; nf < 8; nf++)
            #pragma unroll
            for (int j = 0; j < 4; j++) acc[mt][nf][j] = 0.0f;

    auto issue = [&](int ck, int buf) {
        const int k0 = ck * 32;
        const uint32_t base = sb + buf * BUF_B;
        #pragma unroll
        for (int t = 0; t < 2; t++) {
            const int idx = tid + t * 256;       // 0..511
            const int row = idx >> 2, kc = idx & 3;
            const uint32_t d = base + row * PITCHB + kc * 16;
            const size_t ga = (size_t)(m0 + row) * D_MODEL + k0 + kc * 8;
            const size_t gb = (size_t)(n0 + row) * D_MODEL + k0 + kc * 8;
            cpasync16(d,              Ah + ga);
            cpasync16(d + TILE_B,     Al + ga);
            cpasync16(d + 2 * TILE_B, Wh + gb);
            cpasync16(d + 3 * TILE_B, Wl + gb);
        }
        asm volatile("cp.async.commit_group;" ::: "memory");
    };

    issue(0, 0);
    issue(1, 1);
    int cbuf = 0, ibuf = 2;
    for (int ck = 0; ck < 32; ck++) {
        if (ck + 2 < 32) {
            issue(ck + 2, ibuf);
            ibuf = (ibuf == 2) ? 0 : ibuf + 1;
            asm volatile("cp.async.wait_group 2;" ::: "memory");
        } else if (ck + 1 < 32) {
            asm volatile("cp.async.wait_group 1;" ::: "memory");
        } else {
            asm volatile("cp.async.wait_group 0;" ::: "memory");
        }
        __syncthreads();

        const uint32_t base = sb + cbuf * BUF_B;
        cbuf = (cbuf == 2) ? 0 : cbuf + 1;
        #pragma unroll
        for (int ks = 0; ks < 2; ks++) {
            const int kob = ks * 32;
            uint32_t ah[2][4], al[2][4], bh[8][2], bl[8][2];
            const uint32_t aaddr = base + (wm * 32 + aRow) * PITCHB + kob + aKoff;
            ldsm4(aaddr,                          ah[0][0], ah[0][1], ah[0][2], ah[0][3]);
            ldsm4(aaddr + 16 * PITCHB,            ah[1][0], ah[1][1], ah[1][2], ah[1][3]);
            ldsm4(aaddr + TILE_B,                 al[0][0], al[0][1], al[0][2], al[0][3]);
            ldsm4(aaddr + TILE_B + 16 * PITCHB,   al[1][0], al[1][1], al[1][2], al[1][3]);
            const uint32_t baddr = base + 2 * TILE_B
                                 + (wn * 64 + bRow) * PITCHB + kob + bKoff;
            #pragma unroll
            for (int j = 0; j < 4; j++) {
                ldsm4(baddr + j * 16 * PITCHB,
                      bh[2 * j][0], bh[2 * j][1], bh[2 * j + 1][0], bh[2 * j + 1][1]);
                ldsm4(baddr + j * 16 * PITCHB + TILE_B,
                      bl[2 * j][0], bl[2 * j][1], bl[2 * j + 1][0], bl[2 * j + 1][1]);
            }
            #pragma unroll
            for (int mt = 0; mt < 2; mt++)
                #pragma unroll
                for (int nf = 0; nf < 8; nf++) {
                    mma_bf16(acc[mt][nf], ah[mt], bh[nf]);
                    mma_bf16(acc[mt][nf], ah[mt], bl[nf]);
                    mma_bf16(acc[mt][nf], al[mt], bh[nf]);
                }
        }
        __syncthreads();
    }

    // ---- epilogue ----
    #pragma unroll
    for (int mt = 0; mt < 2; mt++) {
        const int row0 = m0 + wm * 32 + mt * 16 + gr;
        #pragma unroll
        for (int nf = 0; nf < 8; nf++) {
            const int col = n0 + wn * 64 + nf * 8 + gc;
            const float2 b2 = *(const float2*)&bias[col];
            float2 v0, v1;
            v0.x = acc[mt][nf][0] + b2.x;  v0.y = acc[mt][nf][1] + b2.y;
            v1.x = acc[mt][nf][2] + b2.x;  v1.y = acc[mt][nf][3] + b2.y;
            if (!FUSED) {
                *(float2*)&C[(size_t)row0 * D_MODEL + col]       = v0;
                *(float2*)&C[(size_t)(row0 + 8) * D_MODEL + col] = v1;
            } else if (z == 0 || z == 1) {
                if (z == 0) {   // fold softmax scale into Q (exact: pow2)
                    v0.x *= 0.125f; v0.y *= 0.125f; v1.x *= 0.125f; v1.y *= 0.125f;
                }
                uint32_t h0, l0, h1, l1;
                split2(v0.x, v0.y, h0, l0);
                split2(v1.x, v1.y, h1, l1);
                uint32_t* dh = (uint32_t*)((z == 0) ? g_qh : g_kh);
                uint32_t* dl = (uint32_t*)((z == 0) ? g_ql : g_kl);
                const int h = col >> 6, d = col & 63;
                {
                    const int b = row0 >> 11, s = row0 & (SEQ - 1);
                    const size_t idx = ((((size_t)(b * HEADS + h)) * SEQ + s) * DK + d) >> 1;
                    dh[idx] = h0; dl[idx] = l0;
                }
                {
                    const int r1 = row0 + 8;
                    const int b = r1 >> 11, s = r1 & (SEQ - 1);
                    const size_t idx = ((((size_t)(b * HEADS + h)) * SEQ + s) * DK + d) >> 1;
                    dh[idx] = h1; dl[idx] = l1;
                }
            } else {   // z == 2: V transposed [bh][d][s]
                const int h = col >> 6, d = col & 63;
                #pragma unroll
                for (int e = 0; e < 4; e++) {
                    const int rr = row0 + (e >> 1) * 8;
                    const int dd2 = d + (e & 1);
                    const float x = (e == 0) ? v0.x : (e == 1) ? v0.y
                                  : (e == 2) ? v1.x : v1.y;
                    const int b = rr >> 11, s = rr & (SEQ - 1);
                    const size_t idx = (((size_t)(b * HEADS + h)) * DK + dd2) * SEQ + s;
                    const __nv_bfloat16 hx = __float2bfloat16(x);
                    g_vth[idx] = hx;
                    g_vtl[idx] = __float2bfloat16(x - __bfloat162float(hx));
                }
            }
        }
    }
}

// ---------------------------------------------------------------------------
// Tensor-core flash attention. CTA = 128 queries x one (b,h); 8 warps, 256 thr.
// ---------------------------------------------------------------------------
#define AT_PITCH  144
#define ATQ_TILE  (128 * AT_PITCH)           // 18432 (Q hi or lo)
#define ATKV_TILE (64 * AT_PITCH)            // 9216
#define AT_KV0    (2 * ATQ_TILE)             // 36864
#define AT_BUF    (4 * ATKV_TILE)            // 36864 (kh,kl,vh,vl)
#define AT_SMEM   (AT_KV0 + 2 * AT_BUF)      // 110592

__global__ void __launch_bounds__(256) attn_tc()
{
    extern __shared__ char smc[];
    const uint32_t sb = smem_u32(smc);
    const int tid = threadIdx.x;
    const int lane = tid & 31, w = tid >> 5;     // w: 0..7 -> rows 16w..16w+15
    const int gr = lane >> 2, gc = (lane & 3) << 1;
    const int aRow  = lane & 15;
    const int aKoff = (lane >> 4) << 4;
    const int bRow  = ((lane >> 4) << 3) | (lane & 7);
    const int bKoff = ((lane >> 3) & 1) << 4;
    const int qt = blockIdx.x;          // 0..15 (128-row q tiles)
    const int bh = blockIdx.y;          // 0..31

    const __nv_bfloat16* Qh = g_qh + ((size_t)bh * SEQ + qt * 128) * DK;
    const __nv_bfloat16* Ql = g_ql + ((size_t)bh * SEQ + qt * 128) * DK;
    const __nv_bfloat16* Kh = g_kh + (size_t)bh * SEQ * DK;     // [key][d]
    const __nv_bfloat16* Kl = g_kl + (size_t)bh * SEQ * DK;
    const __nv_bfloat16* Vh = g_vth + (size_t)bh * DK * SEQ;    // [d][key]
    const __nv_bfloat16* Vl = g_vtl + (size_t)bh * DK * SEQ;

    // ---- Q tile load (once): 128 rows x 8 chunks x 2 tiles ----
    #pragma unroll
    for (int p = 0; p < 4; p++) {
        const int idx = tid + p * 256;          // 0..1023
        const int row = idx >> 3, ch = idx & 7;
        cpasync16(sb + row * AT_PITCH + ch * 16,            Qh + row * DK + ch * 8);
        cpasync16(sb + ATQ_TILE + row * AT_PITCH + ch * 16, Ql + row * DK + ch * 8);
    }
    asm volatile("cp.async.commit_group;" ::: "memory");

    auto issue_kv = [&](int kt, int buf) {
        const uint32_t base = sb + AT_KV0 + buf * AT_BUF;
        #pragma unroll
        for (int p = 0; p < 2; p++) {
            const int idx = tid + p * 256;      // 0..511
            const int row = idx >> 3, ch = idx & 7;
            const uint32_t d = base + row * AT_PITCH + ch * 16;
            const size_t ko = (size_t)(kt * 64 + row) * DK + ch * 8;
            cpasync16(d,                Kh + ko);
            cpasync16(d + ATKV_TILE,    Kl + ko);
            const size_t vo = (size_t)row * SEQ + kt * 64 + ch * 8;
            cpasync16(d + 2 * ATKV_TILE, Vh + vo);
            cpasync16(d + 3 * ATKV_TILE, Vl + vo);
        }
        asm volatile("cp.async.commit_group;" ::: "memory");
    };

    issue_kv(0, 0);

    float o[8][4];
    float m[2] = { -INFINITY, -INFINITY }, l[2] = { 0.0f, 0.0f };
    #pragma unroll
    for (int nf = 0; nf < 8; nf++)
        #pragma unroll
        for (int j = 0; j < 4; j++) o[nf][j] = 0.0f;

    for (int kt = 0; kt < SEQ / 64; kt++) {
        if (kt < 31) {
            issue_kv(kt + 1, (kt + 1) & 1);
            asm volatile("cp.async.wait_group 1;" ::: "memory");
        } else {
            asm volatile("cp.async.wait_group 0;" ::: "memory");
        }
        __syncthreads();

        const uint32_t base = sb + AT_KV0 + (kt & 1) * AT_BUF;

        // ---- S = Q K^T ----
        float s[8][4];
        #pragma unroll
        for (int nf = 0; nf < 8; nf++)
            #pragma unroll
            for (int j = 0; j < 4; j++) s[nf][j] = 0.0f;

        #pragma unroll
        for (int kk = 0; kk < 4; kk++) {
            uint32_t qa[4], qla[4];
            const uint32_t qaddr = sb + (w * 16 + aRow) * AT_PITCH + kk * 32 + aKoff;
            ldsm4(qaddr,            qa[0],  qa[1],  qa[2],  qa[3]);
            ldsm4(qaddr + ATQ_TILE, qla[0], qla[1], qla[2], qla[3]);
            uint32_t kb[8][2], klb[8][2];
            const uint32_t kaddr = base + bRow * AT_PITCH + kk * 32 + bKoff;
            #pragma unroll
            for (int j = 0; j < 4; j++) {
                ldsm4(kaddr + j * 16 * AT_PITCH,
                      kb[2 * j][0], kb[2 * j][1], kb[2 * j + 1][0], kb[2 * j + 1][1]);
                ldsm4(kaddr + j * 16 * AT_PITCH + ATKV_TILE,
                      klb[2 * j][0], klb[2 * j][1], klb[2 * j + 1][0], klb[2 * j + 1][1]);
            }
            #pragma unroll
            for (int nf = 0; nf < 8; nf++) {
                mma_bf16(s[nf], qa,  kb[nf]);
                mma_bf16(s[nf], qa,  klb[nf]);
                mma_bf16(s[nf], qla, kb[nf]);
            }
        }

        // ---- online softmax (rows gr, gr+8) ----
        #pragma unroll
        for (int r = 0; r < 2; r++) {
            float tm = -INFINITY;
            #pragma unroll
            for (int nf = 0; nf < 8; nf++)
                tm = fmaxf(tm, fmaxf(s[nf][2 * r], s[nf][2 * r + 1]));
            tm = fmaxf(tm, __shfl_xor_sync(0xffffffffu, tm, 1, 4));
            tm = fmaxf(tm, __shfl_xor_sync(0xffffffffu, tm, 2, 4));
            const float mn = fmaxf(m[r], tm);
            const float alpha = __expf(m[r] - mn);
            float rs = 0.0f;
            #pragma unroll
            for (int nf = 0; nf < 8; nf++) {
                float p0 = __expf(s[nf][2 * r]     - mn);
                float p1 = __expf(s[nf][2 * r + 1] - mn);
                s[nf][2 * r] = p0; s[nf][2 * r + 1] = p1;
                rs += p0 + p1;
            }
            rs += __shfl_xor_sync(0xffffffffu, rs, 1, 4);
            rs += __shfl_xor_sync(0xffffffffu, rs, 2, 4);
            l[r] = l[r] * alpha + rs;
            m[r] = mn;
            #pragma unroll
            for (int nf = 0; nf < 8; nf++) {
                o[nf][2 * r]     *= alpha;
                o[nf][2 * r + 1] *= alpha;
            }
        }

        // ---- O += P V ----
        #pragma unroll
        for (int kk = 0; kk < 4; kk++) {
            uint32_t ph[4], pl[4];
            split2(s[2 * kk][0],     s[2 * kk][1],     ph[0], pl[0]);
            split2(s[2 * kk][2],     s[2 * kk][3],     ph[1], pl[1]);
            split2(s[2 * kk + 1][0], s[2 * kk + 1][1], ph[2], pl[2]);
            split2(s[2 * kk + 1][2], s[2 * kk + 1][3], ph[3], pl[3]);
            uint32_t vb[8][2], vlb[8][2];
            const uint32_t vaddr = base + 2 * ATKV_TILE + bRow * AT_PITCH + kk * 32 + bKoff;
            #pragma unroll
            for (int j = 0; j < 4; j++) {
                ldsm4(vaddr + j * 16 * AT_PITCH,
                      vb[2 * j][0], vb[2 * j][1], vb[2 * j + 1][0], vb[2 * j + 1][1]);
                ldsm4(vaddr + j * 16 * AT_PITCH + ATKV_TILE,
                      vlb[2 * j][0], vlb[2 * j][1], vlb[2 * j + 1][0], vlb[2 * j + 1][1]);
            }
            #pragma unroll
            for (int nf = 0; nf < 8; nf++) {
                mma_bf16(o[nf], ph, vb[nf]);
                mma_bf16(o[nf], ph, vlb[nf]);
                mma_bf16(o[nf], pl, vb[nf]);
            }
        }
        __syncthreads();
    }

    // ---- epilogue: normalize, split, write g_ah/g_al [B,S,D_MODEL] ----
    const int b = bh >> 4, h = bh & 15;
    uint32_t* dh = (uint32_t*)g_ah;
    uint32_t* dl = (uint32_t*)g_al;
    #pragma unroll
    for (int r = 0; r < 2; r++) {
        const float inv = 1.0f / l[r];
        const int srow = qt * 128 + w * 16 + gr + 8 * r;
        const size_t rowbase = (size_t)(b * SEQ + srow) * D_MODEL;
        #pragma unroll
        for (int nf = 0; nf < 8; nf++) {
            const float x = o[nf][2 * r] * inv;
            const float y = o[nf][2 * r + 1] * inv;
            uint32_t hi, lo;
            split2(x, y, hi, lo);
            const size_t idx = (rowbase + h * DK + nf * 8 + gc) >> 1;
            dh[idx] = hi; dl[idx] = lo;
        }
    }
}

// ---------------------------------------------------------------------------
extern "C" void kernel_launch(void* const* d_in, const int* in_sizes, int n_in,
                              void* d_out, int out_size)
{
    const float* query = (const float*)d_in[0];
    const float* key_  = (const float*)d_in[1];
    const float* value = (const float*)d_in[2];
    const float* Wq = (const float*)d_in[3];
    const float* bq = (const float*)d_in[4];
    const float* Wk = (const float*)d_in[5];
    const float* bk = (const float*)d_in[6];
    const float* Wv = (const float*)d_in[7];
    const float* bv = (const float*)d_in[8];
    const float* Wo = (const float*)d_in[9];
    const float* bo = (const float*)d_in[10];
    float* out = (float*)d_out;

    cudaFuncSetAttribute(gemm_mma<0>, cudaFuncAttributeMaxDynamicSharedMemorySize, GM_SMEM);
    cudaFuncSetAttribute(gemm_mma<1>, cudaFuncAttributeMaxDynamicSharedMemorySize, GM_SMEM);
    cudaFuncSetAttribute(attn_tc, cudaFuncAttributeMaxDynamicSharedMemorySize, AT_SMEM);

    splitT4_kernel<<<dim3(32, 32, 4), dim3(32, 8)>>>(Wq, Wk, Wv, Wo);
    split3_kernel<<<dim3((MD / 4) / 256, 3), 256>>>(query, key_, value);

    gemm_mma<1><<<dim3(D_MODEL / 128, MROWS / 128, 3), 256, GM_SMEM>>>(bq, bk, bv, nullptr);

    attn_tc<<<dim3(SEQ / 128, BATCH * HEADS), 256, AT_SMEM>>>();

    gemm_mma<0><<<dim3(D_MODEL / 128, MROWS / 128), 256, GM_SMEM>>>(bo, nullptr, nullptr, out);
}